// round 11
// baseline (speedup 1.0000x reference)
#include <cuda_runtime.h>
#include <cuda_bf16.h>
#include <cstdint>

__device__ float g_u_tgt;

// Compute u(target) = MLP(6.2562059, 6.2562059) once per launch.
__global__ void utgt_kernel(const float* __restrict__ W1, const float* __restrict__ b1,
                            const float* __restrict__ W2, const float* __restrict__ b2,
                            const float* __restrict__ W3, const float* __restrict__ b3) {
    __shared__ float h1[64];
    __shared__ float part[64];
    int t = threadIdx.x;
    const float tt = 6.2562059f;
    float h = fmaf(W1[2 * t], tt, fmaf(W1[2 * t + 1], tt, b1[t]));
    h1[t] = fmaxf(h, 0.f);
    __syncthreads();
    float acc = b2[t];
#pragma unroll
    for (int k = 0; k < 64; k++) acc = fmaf(W2[t * 64 + k], h1[k], acc);
    part[t] = W3[t] * fmaxf(acc, 0.f);
    __syncthreads();
    if (t == 0) {
        float s = b3[0];
#pragma unroll
        for (int k = 0; k < 64; k++) s += part[k];
        g_u_tgt = s;
    }
}

__device__ __forceinline__ uint32_t bf16x2(float lo, float hi) {
    __nv_bfloat16 l = __float2bfloat16(lo), h = __float2bfloat16(hi);
    return ((uint32_t)__bfloat16_as_ushort(h) << 16) | __bfloat16_as_ushort(l);
}

// B staging tiles in dynamic smem, 144-byte row pitch (conflict-free ldmatrix)
#define BH_OFF 0u
#define BL_OFF 9216u
#define DSMEM  18432

#define LDSM4(r0, r1, r2, r3, a) \
    asm volatile("ldmatrix.sync.aligned.m8n8.x4.shared.b16 {%0,%1,%2,%3}, [%4];" \
                 : "=r"(r0), "=r"(r1), "=r"(r2), "=r"(r3) : "r"(a))

#define MMA16816(d, a, b0v, b1v) \
    asm volatile("mma.sync.aligned.m16n8k16.row.col.f32.bf16.bf16.f32 " \
                 "{%0,%1,%2,%3}, {%4,%5,%6,%7}, {%8,%9}, {%0,%1,%2,%3};" \
                 : "+f"(d[0]), "+f"(d[1]), "+f"(d[2]), "+f"(d[3]) \
                 : "r"(a[0]), "r"(a[1]), "r"(a[2]), "r"(a[3]), "r"(b0v), "r"(b1v))

__global__ void __launch_bounds__(128, 2) netc_kernel(
    const float* __restrict__ x, const float* __restrict__ y,
    const float* __restrict__ ex, const float* __restrict__ ey,
    const float* __restrict__ W1, const float* __restrict__ b1,
    const float* __restrict__ W2, const float* __restrict__ b2,
    const float* __restrict__ W3, const float* __restrict__ b3,
    float* __restrict__ out, int n, int ntiles) {
    extern __shared__ char dsm[];
    __shared__ float b2s[64], w3s[64];
    __shared__ float w1qA[4 * 17], w1qB[4 * 17], b1q[4 * 17];
    __shared__ float usx[2][128];   // partial layer-3 sums per j-half

    unsigned base = (unsigned)__cvta_generic_to_shared(dsm);
    int tid = threadIdx.x;
    int lane = tid & 31, wid = tid >> 5;
    int q = lane & 3, g = lane >> 2;
    int thalf = wid >> 1;   // token half: warps {0,1} -> tokens [0,64), {2,3} -> [64,128)
    int jhalf = wid & 1;    // neuron half: j in [jhalf*32, jhalf*32+32)

    if (tid < 64) { b2s[tid] = b2[tid]; w3s[tid] = W3[tid]; }
    if (tid < 64) {
        int qq = tid >> 4, li = tid & 15;
        int kk = (li >> 2) * 16 + ((li >> 1) & 1) * 8 + qq * 2 + (li & 1);
        w1qA[qq * 17 + li] = W1[2 * kk];
        w1qB[qq * 17 + li] = W1[2 * kk + 1];
        b1q[qq * 17 + li] = b1[kk];
    }

    // W2 -> bf16 hi/lo staging tiles.
    for (int p = tid; p < 2048; p += 128) {
        int j = p >> 5, kw = p & 31;
        float2 v = ((const float2*)W2)[p];
        __nv_bfloat16 hx = __float2bfloat16(v.x);
        __nv_bfloat16 hy = __float2bfloat16(v.y);
        float fx = __bfloat162float(hx), fy = __bfloat162float(hy);
        uint32_t whi = ((uint32_t)__bfloat16_as_ushort(hy) << 16) | __bfloat16_as_ushort(hx);
        uint32_t wlo = bf16x2(v.x - fx, v.y - fy);
        unsigned off = (unsigned)(j * 144 + kw * 4);
        asm volatile("st.shared.b32 [%0], %1;" :: "r"(base + BH_OFF + off), "r"(whi) : "memory");
        asm volatile("st.shared.b32 [%0], %1;" :: "r"(base + BL_OFF + off), "r"(wlo) : "memory");
    }
    __syncthreads();

    int b_row = lane & 7, b_coff = (lane >> 3) * 16;

    // Hoist B-hi fragments for this warp's 4 n-tiles (loop-invariant, 32 regs).
    uint32_t Bh[4][8];
#pragma unroll
    for (int nt = 0; nt < 4; nt++) {
        unsigned addr = base + BH_OFF + (unsigned)((jhalf * 32 + nt * 8 + b_row) * 144) + b_coff;
        LDSM4(Bh[nt][0], Bh[nt][1], Bh[nt][2], Bh[nt][3], addr);
        LDSM4(Bh[nt][4], Bh[nt][5], Bh[nt][6], Bh[nt][7], addr + 64);
    }

    float ut = g_u_tgt, bias3 = b3[0];
    const float* wAq = &w1qA[q * 17];
    const float* wBq = &w1qB[q * 17];
    const float* bbq = &b1q[q * 17];

    // Preload tile-0 inputs for this lane's 8 fragment token-rows (4 mt x 2 hf).
    int tile = blockIdx.x;
    float ain[4][2], cin[4][2];
    {
        int tb = tile * 128 + thalf * 64 + g;
#pragma unroll
        for (int mt = 0; mt < 4; mt++)
#pragma unroll
            for (int hf = 0; hf < 2; hf++) {
                int idx = min(tb + mt * 16 + hf * 8, n - 1);
                ain[mt][hf] = x[idx] + ex[idx];
                cin[mt][hf] = y[idx] + ey[idx];
            }
    }

    for (; tile < ntiles; tile += gridDim.x) {
        int tok0 = tile * 128 + thalf * 64;
        float na[4][2], nc[4][2];

#pragma unroll
        for (int ch = 0; ch < 2; ch++) {
            // ---- build A hi/lo fragments for mt = 2ch, 2ch+1 (registers only) ----
            uint32_t Ah[2][4][4], Al[2][4][4];
#pragma unroll
            for (int ks = 0; ks < 4; ks++) {
                float wa0 = wAq[ks * 4 + 0], wa1 = wAq[ks * 4 + 1], wa2 = wAq[ks * 4 + 2], wa3 = wAq[ks * 4 + 3];
                float wb0 = wBq[ks * 4 + 0], wb1 = wBq[ks * 4 + 1], wb2 = wBq[ks * 4 + 2], wb3 = wBq[ks * 4 + 3];
                float bb0 = bbq[ks * 4 + 0], bb1 = bbq[ks * 4 + 1], bb2 = bbq[ks * 4 + 2], bb3 = bbq[ks * 4 + 3];
#pragma unroll
                for (int m2 = 0; m2 < 2; m2++) {
#pragma unroll
                    for (int hf = 0; hf < 2; hf++) {
                        float av = ain[ch * 2 + m2][hf], cv = cin[ch * 2 + m2][hf];
                        float v0 = fmaxf(fmaf(wa0, av, fmaf(wb0, cv, bb0)), 0.f);
                        float v1 = fmaxf(fmaf(wa1, av, fmaf(wb1, cv, bb1)), 0.f);
                        float v2 = fmaxf(fmaf(wa2, av, fmaf(wb2, cv, bb2)), 0.f);
                        float v3 = fmaxf(fmaf(wa3, av, fmaf(wb3, cv, bb3)), 0.f);
                        uint32_t h01, h23, l01, l23;
                        asm("cvt.rn.bf16x2.f32 %0, %1, %2;" : "=r"(h01) : "f"(v1), "f"(v0));
                        asm("cvt.rn.bf16x2.f32 %0, %1, %2;" : "=r"(h23) : "f"(v3), "f"(v2));
                        float f0 = __uint_as_float(h01 << 16);
                        float f1 = __uint_as_float(h01 & 0xffff0000u);
                        float f2 = __uint_as_float(h23 << 16);
                        float f3 = __uint_as_float(h23 & 0xffff0000u);
                        asm("cvt.rn.bf16x2.f32 %0, %1, %2;" : "=r"(l01) : "f"(v1 - f1), "f"(v0 - f0));
                        asm("cvt.rn.bf16x2.f32 %0, %1, %2;" : "=r"(l23) : "f"(v3 - f3), "f"(v2 - f2));
                        Ah[m2][ks][hf] = h01;
                        Ah[m2][ks][2 + hf] = h23;
                        Al[m2][ks][hf] = l01;
                        Al[m2][ks][2 + hf] = l23;
                    }
                }
            }

            // Prefetch next tile's inputs once (hidden under first chunk's GEMM).
            if (ch == 0) {
                int ntile = tile + gridDim.x;
                int tb = (ntile < ntiles ? ntile : tile) * 128 + thalf * 64 + g;
#pragma unroll
                for (int mt = 0; mt < 4; mt++)
#pragma unroll
                    for (int hf = 0; hf < 2; hf++) {
                        int idx = min(tb + mt * 16 + hf * 8, n - 1);
                        na[mt][hf] = x[idx] + ex[idx];
                        nc[mt][hf] = y[idx] + ey[idx];
                    }
            }

            // ---- GEMM for this chunk: Ah*Bh + Al*Bh (B in regs) + Ah*Bl (LDSM) ----
            float d[2][4][4];
#pragma unroll
            for (int m2 = 0; m2 < 2; m2++)
#pragma unroll
                for (int nt = 0; nt < 4; nt++)
#pragma unroll
                    for (int r = 0; r < 4; r++) d[m2][nt][r] = 0.f;

#pragma unroll
            for (int nt = 0; nt < 4; nt++) {
#pragma unroll
                for (int m2 = 0; m2 < 2; m2++) {
#pragma unroll
                    for (int ks = 0; ks < 4; ks++) {
                        int bi = (ks >> 1) * 4 + (ks & 1) * 2;
                        MMA16816(d[m2][nt], Ah[m2][ks], Bh[nt][bi], Bh[nt][bi + 1]);
                        MMA16816(d[m2][nt], Al[m2][ks], Bh[nt][bi], Bh[nt][bi + 1]);
                    }
                }
            }
#pragma unroll
            for (int nt = 0; nt < 4; nt++) {
                uint32_t bl[8];
                unsigned addr = base + BL_OFF + (unsigned)((jhalf * 32 + nt * 8 + b_row) * 144) + b_coff;
                LDSM4(bl[0], bl[1], bl[2], bl[3], addr);
                LDSM4(bl[4], bl[5], bl[6], bl[7], addr + 64);
#pragma unroll
                for (int m2 = 0; m2 < 2; m2++) {
#pragma unroll
                    for (int ks = 0; ks < 4; ks++) {
                        int bi = (ks >> 1) * 4 + (ks & 1) * 2;
                        MMA16816(d[m2][nt], Ah[m2][ks], bl[bi], bl[bi + 1]);
                    }
                }
            }

            // ---- partial layer-3 for these 2 m-tiles over this warp's 32 j ----
#pragma unroll
            for (int m2 = 0; m2 < 2; m2++) {
                float s0 = 0.f, s1 = 0.f;
#pragma unroll
                for (int nt = 0; nt < 4; nt++) {
                    int j0 = jhalf * 32 + nt * 8 + 2 * q, j1 = j0 + 1;
                    float w30 = w3s[j0], w31 = w3s[j1];
                    float b20 = b2s[j0], b21 = b2s[j1];
                    s0 = fmaf(w30, fmaxf(d[m2][nt][0] + b20, 0.f), s0);
                    s0 = fmaf(w31, fmaxf(d[m2][nt][1] + b21, 0.f), s0);
                    s1 = fmaf(w30, fmaxf(d[m2][nt][2] + b20, 0.f), s1);
                    s1 = fmaf(w31, fmaxf(d[m2][nt][3] + b21, 0.f), s1);
                }
                s0 += __shfl_xor_sync(0xffffffffu, s0, 1);
                s0 += __shfl_xor_sync(0xffffffffu, s0, 2);
                s1 += __shfl_xor_sync(0xffffffffu, s1, 1);
                s1 += __shfl_xor_sync(0xffffffffu, s1, 2);
                if (q == 0) {
                    int r = thalf * 64 + (ch * 2 + m2) * 16 + g;
                    usx[jhalf][r] = s0;
                    usx[jhalf][r + 8] = s1;
                }
            }
        }

        // ---- pair barrier, combine j-halves, hill epilogue (coalesced) ----
        asm volatile("bar.sync %0, %1;" :: "r"(1 + thalf), "r"(64) : "memory");
        {
            int pl = jhalf * 32 + lane;       // 0..63 within pair
            int tok = tok0 + pl;
            if (tok < n) {
                int r = thalf * 64 + pl;
                float u = usx[0][r] + usx[1][r] + bias3 - ut;
                float xv = x[tok], yv = y[tok];
                float xs = xv * 0.1f, ys = yv * 0.1f;
                float x2 = xs * xs, y2 = ys * ys;
                float ivx = 1.f / (0.25f + x2);
                float ivy = 1.f / (0.25f + y2);
                float hx = x2 * ivx, hy = y2 * ivy;
                float gx = 0.25f * ivx, gy = 0.25f * ivy;
                float dx = 10.f * (hx + 0.2f * gy - 1.1f * xs + u * hx);
                float dy = 10.f * (hy + 0.2f * gx - 1.1f * ys);
                out[tok] = dx;
                out[n + tok] = dy;
                out[2 * n + tok] = -dx;
                out[3 * n + tok] = -dy;
            }
        }
        asm volatile("bar.sync %0, %1;" :: "r"(1 + thalf), "r"(64) : "memory");

#pragma unroll
        for (int mt = 0; mt < 4; mt++)
#pragma unroll
            for (int hf = 0; hf < 2; hf++) { ain[mt][hf] = na[mt][hf]; cin[mt][hf] = nc[mt][hf]; }
    }
}

extern "C" void kernel_launch(void* const* d_in, const int* in_sizes, int n_in,
                              void* d_out, int out_size) {
    const float* x  = (const float*)d_in[0];
    const float* y  = (const float*)d_in[1];
    const float* ex = (const float*)d_in[2];
    const float* ey = (const float*)d_in[3];
    const float* W1 = (const float*)d_in[4];
    const float* b1 = (const float*)d_in[5];
    const float* W2 = (const float*)d_in[6];
    const float* b2 = (const float*)d_in[7];
    const float* W3 = (const float*)d_in[8];
    const float* b3 = (const float*)d_in[9];
    int n = in_sizes[0];
    int ntiles = (n + 127) / 128;

    utgt_kernel<<<1, 64>>>(W1, b1, W2, b2, W3, b3);
    int blocks = 296;  // 2 persistent CTAs per SM
    if (blocks > ntiles) blocks = ntiles;
    netc_kernel<<<blocks, 128, DSMEM>>>(x, y, ex, ey, W1, b1, W2, b2, W3, b3,
                                        (float*)d_out, n, ntiles);
}

// round 12
// speedup vs baseline: 1.1416x; 1.1416x over previous
#include <cuda_runtime.h>
#include <cuda_bf16.h>
#include <cstdint>

__device__ float g_u_tgt;

// Compute u(target) = MLP(6.2562059, 6.2562059) once per launch.
__global__ void utgt_kernel(const float* __restrict__ W1, const float* __restrict__ b1,
                            const float* __restrict__ W2, const float* __restrict__ b2,
                            const float* __restrict__ W3, const float* __restrict__ b3) {
    __shared__ float h1[64];
    __shared__ float part[64];
    int t = threadIdx.x;
    const float tt = 6.2562059f;
    float h = fmaf(W1[2 * t], tt, fmaf(W1[2 * t + 1], tt, b1[t]));
    h1[t] = fmaxf(h, 0.f);
    __syncthreads();
    float acc = b2[t];
#pragma unroll
    for (int k = 0; k < 64; k++) acc = fmaf(W2[t * 64 + k], h1[k], acc);
    part[t] = W3[t] * fmaxf(acc, 0.f);
    __syncthreads();
    if (t == 0) {
        float s = b3[0];
#pragma unroll
        for (int k = 0; k < 64; k++) s += part[k];
        g_u_tgt = s;
    }
}

__device__ __forceinline__ uint32_t bf16x2(float lo, float hi) {
    __nv_bfloat16 l = __float2bfloat16(lo), h = __float2bfloat16(hi);
    return ((uint32_t)__bfloat16_as_ushort(h) << 16) | __bfloat16_as_ushort(l);
}

// B tiles only in dynamic smem, 144-byte row pitch (conflict-free ldmatrix)
#define BH_OFF 0u
#define BL_OFF 9216u
#define DSMEM  18432

#define LDSM4(r0, r1, r2, r3, a) \
    asm volatile("ldmatrix.sync.aligned.m8n8.x4.shared.b16 {%0,%1,%2,%3}, [%4];" \
                 : "=r"(r0), "=r"(r1), "=r"(r2), "=r"(r3) : "r"(a))

#define MMA16816(d, a, b0v, b1v) \
    asm volatile("mma.sync.aligned.m16n8k16.row.col.f32.bf16.bf16.f32 " \
                 "{%0,%1,%2,%3}, {%4,%5,%6,%7}, {%8,%9}, {%0,%1,%2,%3};" \
                 : "+f"(d[0]), "+f"(d[1]), "+f"(d[2]), "+f"(d[3]) \
                 : "r"(a[0]), "r"(a[1]), "r"(a[2]), "r"(a[3]), "r"(b0v), "r"(b1v))

__global__ void __launch_bounds__(128) netc_kernel(
    const float* __restrict__ x, const float* __restrict__ y,
    const float* __restrict__ ex, const float* __restrict__ ey,
    const float* __restrict__ W1, const float* __restrict__ b1,
    const float* __restrict__ W2, const float* __restrict__ b2,
    const float* __restrict__ W3, const float* __restrict__ b3,
    float* __restrict__ out, int n, int ntiles) {
    extern __shared__ char dsm[];
    __shared__ float w1s[128], b1s[64], b2s[64], w3s[64];
    __shared__ float usx[128];

    unsigned base = (unsigned)__cvta_generic_to_shared(dsm);
    int tid = threadIdx.x;
    int lane = tid & 31, wid = tid >> 5;
    int q = lane & 3, g = lane >> 2;

    w1s[tid] = W1[tid];
    if (tid < 64) { b1s[tid] = b1[tid]; b2s[tid] = b2[tid]; w3s[tid] = W3[tid]; }

    // W2 -> bf16 hi/lo B tiles (once per persistent CTA).
    for (int p = tid; p < 2048; p += 128) {
        int j = p >> 5, kw = p & 31;
        float2 v = ((const float2*)W2)[p];
        __nv_bfloat16 hx = __float2bfloat16(v.x);
        __nv_bfloat16 hy = __float2bfloat16(v.y);
        float fx = __bfloat162float(hx), fy = __bfloat162float(hy);
        uint32_t whi = ((uint32_t)__bfloat16_as_ushort(hy) << 16) | __bfloat16_as_ushort(hx);
        uint32_t wlo = bf16x2(v.x - fx, v.y - fy);
        unsigned off = (unsigned)(j * 144 + kw * 4);
        asm volatile("st.shared.b32 [%0], %1;" :: "r"(base + BH_OFF + off), "r"(whi) : "memory");
        asm volatile("st.shared.b32 [%0], %1;" :: "r"(base + BL_OFF + off), "r"(wlo) : "memory");
    }
    __syncthreads();

    float ut = g_u_tgt, bias3 = b3[0];
    int b_row = lane & 7, b_coff = (lane >> 3) * 16;

    // Per-lane layer-1 weights for the 16 fragment k-columns (loop-invariant).
    float wAr[16], wBr[16], bbr[16];
#pragma unroll
    for (int li = 0; li < 16; li++) {
        int kk = (li >> 2) * 16 + ((li >> 1) & 1) * 8 + q * 2 + (li & 1);
        wAr[li] = w1s[2 * kk];
        wBr[li] = w1s[2 * kk + 1];
        bbr[li] = b1s[kk];
    }

    // Preload tile-0 inputs for this lane's 4 fragment token-rows.
    int tile = blockIdx.x;
    float ain[2][2], cin[2][2];
    {
        int tb = tile * 128 + wid * 32 + g;
#pragma unroll
        for (int mt = 0; mt < 2; mt++)
#pragma unroll
            for (int hf = 0; hf < 2; hf++) {
                int idx = min(tb + mt * 16 + hf * 8, n - 1);
                ain[mt][hf] = x[idx] + ex[idx];
                cin[mt][hf] = y[idx] + ey[idx];
            }
    }

    for (; tile < ntiles; tile += gridDim.x) {
        int mytok = tile * 128 + tid;

        // ---- layer 1 + bf16 hi/lo A fragments, all in registers ----
        uint32_t Ah[2][4][4], Al[2][4][4];
#pragma unroll
        for (int mt = 0; mt < 2; mt++) {
#pragma unroll
            for (int hf = 0; hf < 2; hf++) {
                float av = ain[mt][hf], cv = cin[mt][hf];
#pragma unroll
                for (int ks = 0; ks < 4; ks++) {
                    float v0 = fmaxf(fmaf(wAr[ks * 4 + 0], av, fmaf(wBr[ks * 4 + 0], cv, bbr[ks * 4 + 0])), 0.f);
                    float v1 = fmaxf(fmaf(wAr[ks * 4 + 1], av, fmaf(wBr[ks * 4 + 1], cv, bbr[ks * 4 + 1])), 0.f);
                    float v2 = fmaxf(fmaf(wAr[ks * 4 + 2], av, fmaf(wBr[ks * 4 + 2], cv, bbr[ks * 4 + 2])), 0.f);
                    float v3 = fmaxf(fmaf(wAr[ks * 4 + 3], av, fmaf(wBr[ks * 4 + 3], cv, bbr[ks * 4 + 3])), 0.f);
                    uint32_t h01, h23, l01, l23;
                    asm("cvt.rn.bf16x2.f32 %0, %1, %2;" : "=r"(h01) : "f"(v1), "f"(v0));
                    asm("cvt.rn.bf16x2.f32 %0, %1, %2;" : "=r"(h23) : "f"(v3), "f"(v2));
                    float f0 = __uint_as_float(h01 << 16);
                    float f1 = __uint_as_float(h01 & 0xffff0000u);
                    float f2 = __uint_as_float(h23 << 16);
                    float f3 = __uint_as_float(h23 & 0xffff0000u);
                    asm("cvt.rn.bf16x2.f32 %0, %1, %2;" : "=r"(l01) : "f"(v1 - f1), "f"(v0 - f0));
                    asm("cvt.rn.bf16x2.f32 %0, %1, %2;" : "=r"(l23) : "f"(v3 - f3), "f"(v2 - f2));
                    Ah[mt][ks][hf] = h01;
                    Ah[mt][ks][2 + hf] = h23;
                    Al[mt][ks][hf] = l01;
                    Al[mt][ks][2 + hf] = l23;
                }
            }
        }

        // Prefetch next tile's inputs (hidden under the GEMM).
        float na[2][2], nc[2][2];
        int ntile = tile + gridDim.x;
        if (ntile < ntiles) {
            int tb = ntile * 128 + wid * 32 + g;
#pragma unroll
            for (int mt = 0; mt < 2; mt++)
#pragma unroll
                for (int hf = 0; hf < 2; hf++) {
                    int idx = min(tb + mt * 16 + hf * 8, n - 1);
                    na[mt][hf] = x[idx] + ex[idx];
                    nc[mt][hf] = y[idx] + ey[idx];
                }
        } else {
#pragma unroll
            for (int mt = 0; mt < 2; mt++)
#pragma unroll
                for (int hf = 0; hf < 2; hf++) { na[mt][hf] = ain[mt][hf]; nc[mt][hf] = cin[mt][hf]; }
        }

        // ---- GEMM: 3 compensated splits; B per n-tile PAIR from smem.
        //      MMA order ntp -> ks -> (mt, nt2): consecutive MMAs hit 4
        //      distinct accumulators (reuse distance 4, breaks RAW chains) ----
        float d[2][8][4];
#pragma unroll
        for (int mt = 0; mt < 2; mt++)
#pragma unroll
            for (int nt = 0; nt < 8; nt++)
#pragma unroll
                for (int r = 0; r < 4; r++) d[mt][nt][r] = 0.f;

#pragma unroll
        for (int split = 0; split < 3; split++) {
            const uint32_t (*Af)[4][4] = (split == 2) ? Al : Ah;
            unsigned bbase = base + ((split == 1) ? BL_OFF : BH_OFF);
#pragma unroll
            for (int ntp = 0; ntp < 4; ntp++) {
                int nt0 = 2 * ntp, nt1 = 2 * ntp + 1;
                uint32_t bfrA[8], bfrB[8];
                unsigned addrA = bbase + (unsigned)((nt0 * 8 + b_row) * 144) + b_coff;
                unsigned addrB = bbase + (unsigned)((nt1 * 8 + b_row) * 144) + b_coff;
                LDSM4(bfrA[0], bfrA[1], bfrA[2], bfrA[3], addrA);
                LDSM4(bfrA[4], bfrA[5], bfrA[6], bfrA[7], addrA + 64);
                LDSM4(bfrB[0], bfrB[1], bfrB[2], bfrB[3], addrB);
                LDSM4(bfrB[4], bfrB[5], bfrB[6], bfrB[7], addrB + 64);
#pragma unroll
                for (int ks = 0; ks < 4; ks++) {
                    int bi = (ks >> 1) * 4 + (ks & 1) * 2;
                    MMA16816(d[0][nt0], Af[0][ks], bfrA[bi], bfrA[bi + 1]);
                    MMA16816(d[0][nt1], Af[0][ks], bfrB[bi], bfrB[bi + 1]);
                    MMA16816(d[1][nt0], Af[1][ks], bfrA[bi], bfrA[bi + 1]);
                    MMA16816(d[1][nt1], Af[1][ks], bfrB[bi], bfrB[bi + 1]);
                }
            }
        }

        // ---- layer 3 reduction; exchange u through smem for coalesced stores ----
#pragma unroll
        for (int mt = 0; mt < 2; mt++) {
            float s0 = 0.f, s1 = 0.f;
#pragma unroll
            for (int nt = 0; nt < 8; nt++) {
                int j0 = nt * 8 + 2 * q, j1 = j0 + 1;
                float w30 = w3s[j0], w31 = w3s[j1];
                float b20 = b2s[j0], b21 = b2s[j1];
                s0 = fmaf(w30, fmaxf(d[mt][nt][0] + b20, 0.f), s0);
                s0 = fmaf(w31, fmaxf(d[mt][nt][1] + b21, 0.f), s0);
                s1 = fmaf(w30, fmaxf(d[mt][nt][2] + b20, 0.f), s1);
                s1 = fmaf(w31, fmaxf(d[mt][nt][3] + b21, 0.f), s1);
            }
            s0 += __shfl_xor_sync(0xffffffffu, s0, 1);
            s0 += __shfl_xor_sync(0xffffffffu, s0, 2);
            s1 += __shfl_xor_sync(0xffffffffu, s1, 1);
            s1 += __shfl_xor_sync(0xffffffffu, s1, 2);
            if (q == 0) {
                usx[wid * 32 + mt * 16 + g] = s0;
                usx[wid * 32 + mt * 16 + g + 8] = s1;
            }
        }
        __syncwarp();

        if (mytok < n) {
            float xv = x[mytok], yv = y[mytok];
            float u = usx[tid] + bias3 - ut;
            float xs = xv * 0.1f, ys = yv * 0.1f;
            float x2 = xs * xs, y2 = ys * ys;
            float ivx = 1.f / (0.25f + x2);
            float ivy = 1.f / (0.25f + y2);
            float hx = x2 * ivx, hy = y2 * ivy;
            float gx = 0.25f * ivx, gy = 0.25f * ivy;
            float dx = 10.f * (hx + 0.2f * gy - 1.1f * xs + u * hx);
            float dy = 10.f * (hy + 0.2f * gx - 1.1f * ys);
            out[mytok] = dx;
            out[n + mytok] = dy;
            out[2 * n + mytok] = -dx;
            out[3 * n + mytok] = -dy;
        }
        __syncwarp();  // usx reuse guard

#pragma unroll
        for (int mt = 0; mt < 2; mt++)
#pragma unroll
            for (int hf = 0; hf < 2; hf++) { ain[mt][hf] = na[mt][hf]; cin[mt][hf] = nc[mt][hf]; }
    }
}

extern "C" void kernel_launch(void* const* d_in, const int* in_sizes, int n_in,
                              void* d_out, int out_size) {
    const float* x  = (const float*)d_in[0];
    const float* y  = (const float*)d_in[1];
    const float* ex = (const float*)d_in[2];
    const float* ey = (const float*)d_in[3];
    const float* W1 = (const float*)d_in[4];
    const float* b1 = (const float*)d_in[5];
    const float* W2 = (const float*)d_in[6];
    const float* b2 = (const float*)d_in[7];
    const float* W3 = (const float*)d_in[8];
    const float* b3 = (const float*)d_in[9];
    int n = in_sizes[0];
    int ntiles = (n + 127) / 128;

    utgt_kernel<<<1, 64>>>(W1, b1, W2, b2, W3, b3);
    int blocks = 296;  // 2 persistent CTAs per SM
    if (blocks > ntiles) blocks = ntiles;
    netc_kernel<<<blocks, 128, DSMEM>>>(x, y, ex, ey, W1, b1, W2, b2, W3, b3,
                                        (float*)d_out, n, ntiles);
}

// round 13
// speedup vs baseline: 1.4697x; 1.2874x over previous
#include <cuda_runtime.h>
#include <cuda_fp16.h>
#include <cstdint>

__device__ float g_u_tgt;

// Compute u(target) = MLP(6.2562059, 6.2562059) once per launch.
__global__ void utgt_kernel(const float* __restrict__ W1, const float* __restrict__ b1,
                            const float* __restrict__ W2, const float* __restrict__ b2,
                            const float* __restrict__ W3, const float* __restrict__ b3) {
    __shared__ float h1[64];
    __shared__ float part[64];
    int t = threadIdx.x;
    const float tt = 6.2562059f;
    float h = fmaf(W1[2 * t], tt, fmaf(W1[2 * t + 1], tt, b1[t]));
    h1[t] = fmaxf(h, 0.f);
    __syncthreads();
    float acc = b2[t];
#pragma unroll
    for (int k = 0; k < 64; k++) acc = fmaf(W2[t * 64 + k], h1[k], acc);
    part[t] = W3[t] * fmaxf(acc, 0.f);
    __syncthreads();
    if (t == 0) {
        float s = b3[0];
#pragma unroll
        for (int k = 0; k < 64; k++) s += part[k];
        g_u_tgt = s;
    }
}

// B tiles in dynamic smem, 144-byte row pitch (conflict-free ldmatrix)
#define BH_OFF 0u
#define BL_OFF 9216u
#define DSMEM  18432

#define LDSM4(r0, r1, r2, r3, a) \
    asm volatile("ldmatrix.sync.aligned.m8n8.x4.shared.b16 {%0,%1,%2,%3}, [%4];" \
                 : "=r"(r0), "=r"(r1), "=r"(r2), "=r"(r3) : "r"(a))

#define MMAF16(d, a, b0v, b1v) \
    asm volatile("mma.sync.aligned.m16n8k16.row.col.f32.f16.f16.f32 " \
                 "{%0,%1,%2,%3}, {%4,%5,%6,%7}, {%8,%9}, {%0,%1,%2,%3};" \
                 : "+f"(d[0]), "+f"(d[1]), "+f"(d[2]), "+f"(d[3]) \
                 : "r"(a[0]), "r"(a[1]), "r"(a[2]), "r"(a[3]), "r"(b0v), "r"(b1v))

__global__ void __launch_bounds__(128) netc_kernel(
    const float* __restrict__ x, const float* __restrict__ y,
    const float* __restrict__ ex, const float* __restrict__ ey,
    const float* __restrict__ W1, const float* __restrict__ b1,
    const float* __restrict__ W2, const float* __restrict__ b2,
    const float* __restrict__ W3, const float* __restrict__ b3,
    float* __restrict__ out, int n, int ntiles) {
    extern __shared__ char dsm[];
    __shared__ float w1s[128], b1s[64], b2s[64], w3s[64];
    __shared__ float usx[128];

    unsigned base = (unsigned)__cvta_generic_to_shared(dsm);
    int tid = threadIdx.x;
    int lane = tid & 31, wid = tid >> 5;
    int q = lane & 3, g = lane >> 2;

    w1s[tid] = W1[tid];
    if (tid < 64) { b1s[tid] = b1[tid]; b2s[tid] = b2[tid]; w3s[tid] = W3[tid]; }

    // W2 -> fp16 hi/lo B tiles (once per persistent CTA).
    for (int p = tid; p < 2048; p += 128) {
        int j = p >> 5, kw = p & 31;
        float2 v = ((const float2*)W2)[p];
        __half hx = __float2half_rn(v.x);
        __half hy = __float2half_rn(v.y);
        __half lx = __float2half_rn(v.x - __half2float(hx));
        __half ly = __float2half_rn(v.y - __half2float(hy));
        uint32_t whi = ((uint32_t)__half_as_ushort(hy) << 16) | __half_as_ushort(hx);
        uint32_t wlo = ((uint32_t)__half_as_ushort(ly) << 16) | __half_as_ushort(lx);
        unsigned off = (unsigned)(j * 144 + kw * 4);
        asm volatile("st.shared.b32 [%0], %1;" :: "r"(base + BH_OFF + off), "r"(whi) : "memory");
        asm volatile("st.shared.b32 [%0], %1;" :: "r"(base + BL_OFF + off), "r"(wlo) : "memory");
    }
    __syncthreads();

    float ut = g_u_tgt, bias3 = b3[0];
    int b_row = lane & 7, b_coff = (lane >> 3) * 16;

    // Per-lane layer-1 weights for the 16 fragment k-columns (loop-invariant).
    float wAr[16], wBr[16], bbr[16];
#pragma unroll
    for (int li = 0; li < 16; li++) {
        int kk = (li >> 2) * 16 + ((li >> 1) & 1) * 8 + q * 2 + (li & 1);
        wAr[li] = w1s[2 * kk];
        wBr[li] = w1s[2 * kk + 1];
        bbr[li] = b1s[kk];
    }

    // Preload tile-0 inputs for this lane's 4 fragment token-rows.
    int tile = blockIdx.x;
    float ain[2][2], cin[2][2];
    {
        int tb = tile * 128 + wid * 32 + g;
#pragma unroll
        for (int mt = 0; mt < 2; mt++)
#pragma unroll
            for (int hf = 0; hf < 2; hf++) {
                int idx = min(tb + mt * 16 + hf * 8, n - 1);
                ain[mt][hf] = x[idx] + ex[idx];
                cin[mt][hf] = y[idx] + ey[idx];
            }
    }

    for (; tile < ntiles; tile += gridDim.x) {
        int mytok = tile * 128 + tid;

        // ---- layer 1 + single-fp16 A fragments, all in registers ----
        uint32_t Ah[2][4][4];
#pragma unroll
        for (int mt = 0; mt < 2; mt++) {
#pragma unroll
            for (int hf = 0; hf < 2; hf++) {
                float av = ain[mt][hf], cv = cin[mt][hf];
#pragma unroll
                for (int ks = 0; ks < 4; ks++) {
                    float v0 = fmaxf(fmaf(wAr[ks * 4 + 0], av, fmaf(wBr[ks * 4 + 0], cv, bbr[ks * 4 + 0])), 0.f);
                    float v1 = fmaxf(fmaf(wAr[ks * 4 + 1], av, fmaf(wBr[ks * 4 + 1], cv, bbr[ks * 4 + 1])), 0.f);
                    float v2 = fmaxf(fmaf(wAr[ks * 4 + 2], av, fmaf(wBr[ks * 4 + 2], cv, bbr[ks * 4 + 2])), 0.f);
                    float v3 = fmaxf(fmaf(wAr[ks * 4 + 3], av, fmaf(wBr[ks * 4 + 3], cv, bbr[ks * 4 + 3])), 0.f);
                    uint32_t h01, h23;
                    asm("cvt.rn.f16x2.f32 %0, %1, %2;" : "=r"(h01) : "f"(v1), "f"(v0));
                    asm("cvt.rn.f16x2.f32 %0, %1, %2;" : "=r"(h23) : "f"(v3), "f"(v2));
                    Ah[mt][ks][hf] = h01;
                    Ah[mt][ks][2 + hf] = h23;
                }
            }
        }

        // Prefetch next tile's inputs (hidden under the GEMM).
        float na[2][2], nc[2][2];
        int ntile = tile + gridDim.x;
        if (ntile < ntiles) {
            int tb = ntile * 128 + wid * 32 + g;
#pragma unroll
            for (int mt = 0; mt < 2; mt++)
#pragma unroll
                for (int hf = 0; hf < 2; hf++) {
                    int idx = min(tb + mt * 16 + hf * 8, n - 1);
                    na[mt][hf] = x[idx] + ex[idx];
                    nc[mt][hf] = y[idx] + ey[idx];
                }
        } else {
#pragma unroll
            for (int mt = 0; mt < 2; mt++)
#pragma unroll
                for (int hf = 0; hf < 2; hf++) { na[mt][hf] = ain[mt][hf]; nc[mt][hf] = cin[mt][hf]; }
        }

        // ---- GEMM: 2 splits (A*Bh + A*Bl); B per n-tile pair from smem ----
        float d[2][8][4];
#pragma unroll
        for (int mt = 0; mt < 2; mt++)
#pragma unroll
            for (int nt = 0; nt < 8; nt++)
#pragma unroll
                for (int r = 0; r < 4; r++) d[mt][nt][r] = 0.f;

#pragma unroll
        for (int split = 0; split < 2; split++) {
            unsigned bbase = base + ((split == 1) ? BL_OFF : BH_OFF);
#pragma unroll
            for (int ntp = 0; ntp < 4; ntp++) {
                int nt0 = 2 * ntp, nt1 = 2 * ntp + 1;
                uint32_t bfrA[8], bfrB[8];
                unsigned addrA = bbase + (unsigned)((nt0 * 8 + b_row) * 144) + b_coff;
                unsigned addrB = bbase + (unsigned)((nt1 * 8 + b_row) * 144) + b_coff;
                LDSM4(bfrA[0], bfrA[1], bfrA[2], bfrA[3], addrA);
                LDSM4(bfrA[4], bfrA[5], bfrA[6], bfrA[7], addrA + 64);
                LDSM4(bfrB[0], bfrB[1], bfrB[2], bfrB[3], addrB);
                LDSM4(bfrB[4], bfrB[5], bfrB[6], bfrB[7], addrB + 64);
#pragma unroll
                for (int ks = 0; ks < 4; ks++) {
                    int bi = (ks >> 1) * 4 + (ks & 1) * 2;
                    MMAF16(d[0][nt0], Ah[0][ks], bfrA[bi], bfrA[bi + 1]);
                    MMAF16(d[0][nt1], Ah[0][ks], bfrB[bi], bfrB[bi + 1]);
                    MMAF16(d[1][nt0], Ah[1][ks], bfrA[bi], bfrA[bi + 1]);
                    MMAF16(d[1][nt1], Ah[1][ks], bfrB[bi], bfrB[bi + 1]);
                }
            }
        }

        // ---- layer 3 reduction; exchange u through smem for coalesced stores ----
#pragma unroll
        for (int mt = 0; mt < 2; mt++) {
            float s0 = 0.f, s1 = 0.f;
#pragma unroll
            for (int nt = 0; nt < 8; nt++) {
                int j0 = nt * 8 + 2 * q, j1 = j0 + 1;
                float w30 = w3s[j0], w31 = w3s[j1];
                float b20 = b2s[j0], b21 = b2s[j1];
                s0 = fmaf(w30, fmaxf(d[mt][nt][0] + b20, 0.f), s0);
                s0 = fmaf(w31, fmaxf(d[mt][nt][1] + b21, 0.f), s0);
                s1 = fmaf(w30, fmaxf(d[mt][nt][2] + b20, 0.f), s1);
                s1 = fmaf(w31, fmaxf(d[mt][nt][3] + b21, 0.f), s1);
            }
            s0 += __shfl_xor_sync(0xffffffffu, s0, 1);
            s0 += __shfl_xor_sync(0xffffffffu, s0, 2);
            s1 += __shfl_xor_sync(0xffffffffu, s1, 1);
            s1 += __shfl_xor_sync(0xffffffffu, s1, 2);
            if (q == 0) {
                usx[wid * 32 + mt * 16 + g] = s0;
                usx[wid * 32 + mt * 16 + g + 8] = s1;
            }
        }
        __syncwarp();

        if (mytok < n) {
            float xv = x[mytok], yv = y[mytok];
            float u = usx[tid] + bias3 - ut;
            float xs = xv * 0.1f, ys = yv * 0.1f;
            float x2 = xs * xs, y2 = ys * ys;
            float ivx = 1.f / (0.25f + x2);
            float ivy = 1.f / (0.25f + y2);
            float hx = x2 * ivx, hy = y2 * ivy;
            float gx = 0.25f * ivx, gy = 0.25f * ivy;
            float dx = 10.f * (hx + 0.2f * gy - 1.1f * xs + u * hx);
            float dy = 10.f * (hy + 0.2f * gx - 1.1f * ys);
            out[mytok] = dx;
            out[n + mytok] = dy;
            out[2 * n + mytok] = -dx;
            out[3 * n + mytok] = -dy;
        }
        __syncwarp();  // usx reuse guard

#pragma unroll
        for (int mt = 0; mt < 2; mt++)
#pragma unroll
            for (int hf = 0; hf < 2; hf++) { ain[mt][hf] = na[mt][hf]; cin[mt][hf] = nc[mt][hf]; }
    }
}

extern "C" void kernel_launch(void* const* d_in, const int* in_sizes, int n_in,
                              void* d_out, int out_size) {
    const float* x  = (const float*)d_in[0];
    const float* y  = (const float*)d_in[1];
    const float* ex = (const float*)d_in[2];
    const float* ey = (const float*)d_in[3];
    const float* W1 = (const float*)d_in[4];
    const float* b1 = (const float*)d_in[5];
    const float* W2 = (const float*)d_in[6];
    const float* b2 = (const float*)d_in[7];
    const float* W3 = (const float*)d_in[8];
    const float* b3 = (const float*)d_in[9];
    int n = in_sizes[0];
    int ntiles = (n + 127) / 128;

    utgt_kernel<<<1, 64>>>(W1, b1, W2, b2, W3, b3);
    int blocks = 296;  // 2 persistent CTAs per SM
    if (blocks > ntiles) blocks = ntiles;
    netc_kernel<<<blocks, 128, DSMEM>>>(x, y, ex, ey, W1, b1, W2, b2, W3, b3,
                                        (float*)d_out, n, ntiles);
}

// round 14
// speedup vs baseline: 1.5213x; 1.0351x over previous
#include <cuda_runtime.h>
#include <cuda_fp16.h>
#include <cstdint>

__device__ float g_u_tgt;

// Compute u(target) = MLP(6.2562059, 6.2562059) once per launch.
__global__ void utgt_kernel(const float* __restrict__ W1, const float* __restrict__ b1,
                            const float* __restrict__ W2, const float* __restrict__ b2,
                            const float* __restrict__ W3, const float* __restrict__ b3) {
    __shared__ float h1[64];
    __shared__ float part[64];
    int t = threadIdx.x;
    const float tt = 6.2562059f;
    float h = fmaf(W1[2 * t], tt, fmaf(W1[2 * t + 1], tt, b1[t]));
    h1[t] = fmaxf(h, 0.f);
    __syncthreads();
    float acc = b2[t];
#pragma unroll
    for (int k = 0; k < 64; k++) acc = fmaf(W2[t * 64 + k], h1[k], acc);
    part[t] = W3[t] * fmaxf(acc, 0.f);
    __syncthreads();
    if (t == 0) {
        float s = b3[0];
#pragma unroll
        for (int k = 0; k < 64; k++) s += part[k];
        g_u_tgt = s;
    }
}

// B tiles in dynamic smem, 144-byte row pitch (conflict-free ldmatrix)
#define BH_OFF 0u
#define BL_OFF 9216u
#define DSMEM  18432

#define LDSM4(r0, r1, r2, r3, a) \
    asm volatile("ldmatrix.sync.aligned.m8n8.x4.shared.b16 {%0,%1,%2,%3}, [%4];" \
                 : "=r"(r0), "=r"(r1), "=r"(r2), "=r"(r3) : "r"(a))

#define MMAF16(d, a, b0v, b1v) \
    asm volatile("mma.sync.aligned.m16n8k16.row.col.f32.f16.f16.f32 " \
                 "{%0,%1,%2,%3}, {%4,%5,%6,%7}, {%8,%9}, {%0,%1,%2,%3};" \
                 : "+f"(d[0]), "+f"(d[1]), "+f"(d[2]), "+f"(d[3]) \
                 : "r"(a[0]), "r"(a[1]), "r"(a[2]), "r"(a[3]), "r"(b0v), "r"(b1v))

__global__ void __launch_bounds__(128, 3) netc_kernel(
    const float* __restrict__ x, const float* __restrict__ y,
    const float* __restrict__ ex, const float* __restrict__ ey,
    const float* __restrict__ W1, const float* __restrict__ b1,
    const float* __restrict__ W2, const float* __restrict__ b2,
    const float* __restrict__ W3, const float* __restrict__ b3,
    float* __restrict__ out, int n, int ntiles) {
    extern __shared__ char dsm[];
    __shared__ float w1s[128], b1s[64], b2s[64], w3s[64];
    __shared__ float usx[128];

    unsigned base = (unsigned)__cvta_generic_to_shared(dsm);
    int tid = threadIdx.x;
    int lane = tid & 31, wid = tid >> 5;
    int q = lane & 3, g = lane >> 2;

    w1s[tid] = W1[tid];
    if (tid < 64) { b1s[tid] = b1[tid]; b2s[tid] = b2[tid]; w3s[tid] = W3[tid]; }

    // W2 -> fp16 hi/lo B tiles (once per persistent CTA).
    for (int p = tid; p < 2048; p += 128) {
        int j = p >> 5, kw = p & 31;
        float2 v = ((const float2*)W2)[p];
        __half hx = __float2half_rn(v.x);
        __half hy = __float2half_rn(v.y);
        __half lx = __float2half_rn(v.x - __half2float(hx));
        __half ly = __float2half_rn(v.y - __half2float(hy));
        uint32_t whi = ((uint32_t)__half_as_ushort(hy) << 16) | __half_as_ushort(hx);
        uint32_t wlo = ((uint32_t)__half_as_ushort(ly) << 16) | __half_as_ushort(lx);
        unsigned off = (unsigned)(j * 144 + kw * 4);
        asm volatile("st.shared.b32 [%0], %1;" :: "r"(base + BH_OFF + off), "r"(whi) : "memory");
        asm volatile("st.shared.b32 [%0], %1;" :: "r"(base + BL_OFF + off), "r"(wlo) : "memory");
    }
    __syncthreads();

    float ut = g_u_tgt, bias3 = b3[0];
    int b_row = lane & 7, b_coff = (lane >> 3) * 16;

    // Per-lane layer-1 weights for the 16 fragment k-columns (loop-invariant).
    float wAr[16], wBr[16], bbr[16];
#pragma unroll
    for (int li = 0; li < 16; li++) {
        int kk = (li >> 2) * 16 + ((li >> 1) & 1) * 8 + q * 2 + (li & 1);
        wAr[li] = w1s[2 * kk];
        wBr[li] = w1s[2 * kk + 1];
        bbr[li] = b1s[kk];
    }

    // Preload tile-0 inputs for this lane's 4 fragment token-rows.
    int tile = blockIdx.x;
    float ain[2][2], cin[2][2];
    {
        int tb = tile * 128 + wid * 32 + g;
#pragma unroll
        for (int mt = 0; mt < 2; mt++)
#pragma unroll
            for (int hf = 0; hf < 2; hf++) {
                int idx = min(tb + mt * 16 + hf * 8, n - 1);
                ain[mt][hf] = x[idx] + ex[idx];
                cin[mt][hf] = y[idx] + ey[idx];
            }
    }

    for (; tile < ntiles; tile += gridDim.x) {
        int mytok = tile * 128 + tid;

        // ---- layer 1 + single-fp16 A fragments, all in registers ----
        uint32_t Ah[2][4][4];
#pragma unroll
        for (int mt = 0; mt < 2; mt++) {
#pragma unroll
            for (int hf = 0; hf < 2; hf++) {
                float av = ain[mt][hf], cv = cin[mt][hf];
#pragma unroll
                for (int ks = 0; ks < 4; ks++) {
                    float v0 = fmaxf(fmaf(wAr[ks * 4 + 0], av, fmaf(wBr[ks * 4 + 0], cv, bbr[ks * 4 + 0])), 0.f);
                    float v1 = fmaxf(fmaf(wAr[ks * 4 + 1], av, fmaf(wBr[ks * 4 + 1], cv, bbr[ks * 4 + 1])), 0.f);
                    float v2 = fmaxf(fmaf(wAr[ks * 4 + 2], av, fmaf(wBr[ks * 4 + 2], cv, bbr[ks * 4 + 2])), 0.f);
                    float v3 = fmaxf(fmaf(wAr[ks * 4 + 3], av, fmaf(wBr[ks * 4 + 3], cv, bbr[ks * 4 + 3])), 0.f);
                    uint32_t h01, h23;
                    asm("cvt.rn.f16x2.f32 %0, %1, %2;" : "=r"(h01) : "f"(v1), "f"(v0));
                    asm("cvt.rn.f16x2.f32 %0, %1, %2;" : "=r"(h23) : "f"(v3), "f"(v2));
                    Ah[mt][ks][hf] = h01;
                    Ah[mt][ks][2 + hf] = h23;
                }
            }
        }

        // Prefetch next tile's inputs (hidden under the GEMM).
        float na[2][2], nc[2][2];
        int ntile = tile + gridDim.x;
        if (ntile < ntiles) {
            int tb = ntile * 128 + wid * 32 + g;
#pragma unroll
            for (int mt = 0; mt < 2; mt++)
#pragma unroll
                for (int hf = 0; hf < 2; hf++) {
                    int idx = min(tb + mt * 16 + hf * 8, n - 1);
                    na[mt][hf] = x[idx] + ex[idx];
                    nc[mt][hf] = y[idx] + ey[idx];
                }
        } else {
#pragma unroll
            for (int mt = 0; mt < 2; mt++)
#pragma unroll
                for (int hf = 0; hf < 2; hf++) { na[mt][hf] = ain[mt][hf]; nc[mt][hf] = cin[mt][hf]; }
        }

        // ---- GEMM + interleaved layer-3: ntp outer, split inner.
        //      d is transient per n-tile pair (16 regs); layer-3 partials
        //      accumulate into 4 carried registers s[mt][half]. ----
        float s00 = 0.f, s01 = 0.f, s10 = 0.f, s11 = 0.f;
#pragma unroll
        for (int ntp = 0; ntp < 4; ntp++) {
            int nt0 = 2 * ntp, nt1 = 2 * ntp + 1;
            float d[2][2][4];
#pragma unroll
            for (int mt = 0; mt < 2; mt++)
#pragma unroll
                for (int n2 = 0; n2 < 2; n2++)
#pragma unroll
                    for (int r = 0; r < 4; r++) d[mt][n2][r] = 0.f;

            uint32_t bfrA[8], bfrB[8];
            unsigned rowA = (unsigned)((nt0 * 8 + b_row) * 144) + b_coff;
            unsigned rowB = (unsigned)((nt1 * 8 + b_row) * 144) + b_coff;

            // hi split
            LDSM4(bfrA[0], bfrA[1], bfrA[2], bfrA[3], base + BH_OFF + rowA);
            LDSM4(bfrA[4], bfrA[5], bfrA[6], bfrA[7], base + BH_OFF + rowA + 64);
            LDSM4(bfrB[0], bfrB[1], bfrB[2], bfrB[3], base + BH_OFF + rowB);
            LDSM4(bfrB[4], bfrB[5], bfrB[6], bfrB[7], base + BH_OFF + rowB + 64);
#pragma unroll
            for (int ks = 0; ks < 4; ks++) {
                int bi = (ks >> 1) * 4 + (ks & 1) * 2;
                MMAF16(d[0][0], Ah[0][ks], bfrA[bi], bfrA[bi + 1]);
                MMAF16(d[0][1], Ah[0][ks], bfrB[bi], bfrB[bi + 1]);
                MMAF16(d[1][0], Ah[1][ks], bfrA[bi], bfrA[bi + 1]);
                MMAF16(d[1][1], Ah[1][ks], bfrB[bi], bfrB[bi + 1]);
            }
            // lo split (reuse fragment registers)
            LDSM4(bfrA[0], bfrA[1], bfrA[2], bfrA[3], base + BL_OFF + rowA);
            LDSM4(bfrA[4], bfrA[5], bfrA[6], bfrA[7], base + BL_OFF + rowA + 64);
            LDSM4(bfrB[0], bfrB[1], bfrB[2], bfrB[3], base + BL_OFF + rowB);
            LDSM4(bfrB[4], bfrB[5], bfrB[6], bfrB[7], base + BL_OFF + rowB + 64);
#pragma unroll
            for (int ks = 0; ks < 4; ks++) {
                int bi = (ks >> 1) * 4 + (ks & 1) * 2;
                MMAF16(d[0][0], Ah[0][ks], bfrA[bi], bfrA[bi + 1]);
                MMAF16(d[0][1], Ah[0][ks], bfrB[bi], bfrB[bi + 1]);
                MMAF16(d[1][0], Ah[1][ks], bfrA[bi], bfrA[bi + 1]);
                MMAF16(d[1][1], Ah[1][ks], bfrB[bi], bfrB[bi + 1]);
            }

            // layer-3 partial for these 2 n-tiles
#pragma unroll
            for (int n2 = 0; n2 < 2; n2++) {
                int j0 = (nt0 + n2) * 8 + 2 * q, j1 = j0 + 1;
                float w30 = w3s[j0], w31 = w3s[j1];
                float b20 = b2s[j0], b21 = b2s[j1];
                s00 = fmaf(w30, fmaxf(d[0][n2][0] + b20, 0.f), s00);
                s00 = fmaf(w31, fmaxf(d[0][n2][1] + b21, 0.f), s00);
                s01 = fmaf(w30, fmaxf(d[0][n2][2] + b20, 0.f), s01);
                s01 = fmaf(w31, fmaxf(d[0][n2][3] + b21, 0.f), s01);
                s10 = fmaf(w30, fmaxf(d[1][n2][0] + b20, 0.f), s10);
                s10 = fmaf(w31, fmaxf(d[1][n2][1] + b21, 0.f), s10);
                s11 = fmaf(w30, fmaxf(d[1][n2][2] + b20, 0.f), s11);
                s11 = fmaf(w31, fmaxf(d[1][n2][3] + b21, 0.f), s11);
            }
        }

        // ---- reduce over the 4 q-lanes, exchange via smem ----
        s00 += __shfl_xor_sync(0xffffffffu, s00, 1);
        s00 += __shfl_xor_sync(0xffffffffu, s00, 2);
        s01 += __shfl_xor_sync(0xffffffffu, s01, 1);
        s01 += __shfl_xor_sync(0xffffffffu, s01, 2);
        s10 += __shfl_xor_sync(0xffffffffu, s10, 1);
        s10 += __shfl_xor_sync(0xffffffffu, s10, 2);
        s11 += __shfl_xor_sync(0xffffffffu, s11, 1);
        s11 += __shfl_xor_sync(0xffffffffu, s11, 2);
        if (q == 0) {
            usx[wid * 32 + g] = s00;
            usx[wid * 32 + g + 8] = s01;
            usx[wid * 32 + 16 + g] = s10;
            usx[wid * 32 + 16 + g + 8] = s11;
        }
        __syncwarp();

        if (mytok < n) {
            float xv = x[mytok], yv = y[mytok];
            float u = usx[tid] + bias3 - ut;
            float xs = xv * 0.1f, ys = yv * 0.1f;
            float x2 = xs * xs, y2 = ys * ys;
            float ivx = 1.f / (0.25f + x2);
            float ivy = 1.f / (0.25f + y2);
            float hx = x2 * ivx, hy = y2 * ivy;
            float gx = 0.25f * ivx, gy = 0.25f * ivy;
            float dx = 10.f * (hx + 0.2f * gy - 1.1f * xs + u * hx);
            float dy = 10.f * (hy + 0.2f * gx - 1.1f * ys);
            out[mytok] = dx;
            out[n + mytok] = dy;
            out[2 * n + mytok] = -dx;
            out[3 * n + mytok] = -dy;
        }
        __syncwarp();  // usx reuse guard

#pragma unroll
        for (int mt = 0; mt < 2; mt++)
#pragma unroll
            for (int hf = 0; hf < 2; hf++) { ain[mt][hf] = na[mt][hf]; cin[mt][hf] = nc[mt][hf]; }
    }
}

extern "C" void kernel_launch(void* const* d_in, const int* in_sizes, int n_in,
                              void* d_out, int out_size) {
    const float* x  = (const float*)d_in[0];
    const float* y  = (const float*)d_in[1];
    const float* ex = (const float*)d_in[2];
    const float* ey = (const float*)d_in[3];
    const float* W1 = (const float*)d_in[4];
    const float* b1 = (const float*)d_in[5];
    const float* W2 = (const float*)d_in[6];
    const float* b2 = (const float*)d_in[7];
    const float* W3 = (const float*)d_in[8];
    const float* b3 = (const float*)d_in[9];
    int n = in_sizes[0];
    int ntiles = (n + 127) / 128;

    utgt_kernel<<<1, 64>>>(W1, b1, W2, b2, W3, b3);
    int blocks = 444;  // 3 persistent CTAs per SM
    if (blocks > ntiles) blocks = ntiles;
    netc_kernel<<<blocks, 128, DSMEM>>>(x, y, ex, ey, W1, b1, W2, b2, W3, b3,
                                        (float*)d_out, n, ntiles);
}